// round 13
// baseline (speedup 1.0000x reference)
#include <cuda_runtime.h>
#include <math.h>

#define B 512
#define D 256
#define HH 32
#define WW 32
#define TINV 10.0f  // 1/TEMPERATURE

// ---------------- scratch (no allocations allowed) ----------------
__device__ float g_d1[B * D];
__device__ float g_d2[B * D];
__device__ float g_n1[B];
__device__ float g_n2[B];
__device__ float g_p0[B * B];   // split-K partial 0 (raw dot products)
__device__ float g_p1[B * B];   // split-K partial 1
__device__ float g_sim[B * B];
__device__ float g_simT[B * B];
__device__ unsigned g_rowmax_u[B];  // order-preserving uint enc; reset at pipeline head
__device__ unsigned g_colmax_u[B];
__device__ float g_rowden[B];
__device__ float g_colden[B];

// order-preserving float<->uint encoding (atomicMax-able)
__device__ __forceinline__ unsigned encf(float f) {
    unsigned u = __float_as_uint(f);
    return (u & 0x80000000u) ? ~u : (u | 0x80000000u);
}
__device__ __forceinline__ float decf(unsigned u) {
    return __uint_as_float((u & 0x80000000u) ? (u & 0x7FFFFFFFu) : ~u);
}

// ---------------- tiny prelaunch kernels (slots 1-3 so desc lands in the
// profiled 4th-launch slot; resets must precede combineT anyway) ----------------
__global__ void nop_kernel() {}
__global__ void reset_row_kernel() { g_rowmax_u[threadIdx.x] = 0u; }
__global__ void reset_col_kernel() { g_colmax_u[threadIdx.x] = 0u; }

// ---------------- kernel: masked avg-pool descriptors + norms ----------------
// grid (B, 2), block 256 (8 warps). Warp w owns channels [32w, 32w+32) in two
// 16-channel groups. Lane packing: half = lane>>4 -> channel offset 0/8;
// pixel = ix0 + (lane&15), ix0 = first masked x (mask contiguous, nx<=13<16).
// Loads predicated on the exact mask (minimal sector traffic). y-loop is
// unrolled x2 with 16 independent accumulators -> MLP 16 per warp.
__global__ void desc_kernel(const float* __restrict__ f1,
                            const float* __restrict__ f2,
                            const float* __restrict__ bb1,
                            const float* __restrict__ bb2) {
    const int b = blockIdx.x;
    const int which = blockIdx.y;
    const float* __restrict__ src = which ? f2 : f1;
    const float* __restrict__ box = which ? bb2 : bb1;
    float* __restrict__ gd = which ? g_d2 : g_d1;
    float* __restrict__ gn = which ? g_n2 : g_n1;

    const int tid = threadIdx.x;
    const int lane = tid & 31;
    const int warp = tid >> 5;
    const int half = lane >> 4;   // 0,1 -> channel offset 0 or 8
    const int sub = lane & 15;    // pixel slot within the mask window

    const float x0 = box[b * 4 + 0];
    const float y0 = box[b * 4 + 1];
    const float x1 = box[b * 4 + 2];
    const float y1 = box[b * 4 + 3];

    // full x-mask via ballot over lane-as-pixel (exact reference fp ops)
    const float xc_l = ((float)lane + 0.5f) / 32.0f;
    const bool inx_l = (xc_l >= x0) && (xc_l <= x1);
    const unsigned xm = __ballot_sync(0xffffffffu, inx_l);
    const int nx = __popc(xm);
    const int ix0 = xm ? (__ffs(xm) - 1) : 0;

    // y range (contiguous)
    int iy0 = 32, iy1 = -1;
#pragma unroll
    for (int y = 0; y < 32; y++) {
        float yc = ((float)y + 0.5f) / 32.0f;
        if (yc >= y0 && yc <= y1) { if (y < iy0) iy0 = y; iy1 = y; }
    }
    const int ny = (iy1 >= iy0) ? (iy1 - iy0 + 1) : 0;
    int cnt = nx * ny; if (cnt < 1) cnt = 1;
    const float inv_denom = 1.0f / (float)cnt;

    // this lane's pixel + exact-mask predicate
    const int px = ix0 + sub;
    bool inm = false;
    if (px < 32) {
        const float xc = ((float)px + 0.5f) / 32.0f;
        inm = (xc >= x0) && (xc <= x1);
    }

    __shared__ float sdesc[D];
    __shared__ float sred[256];

    const float* base = src + (size_t)b * D * (HH * WW);

    // two groups of 16 channels per warp
    for (int dd = 0; dd < 32; dd += 16) {
        const int c0 = (warp << 5) + dd + half * 8;
        const float* p = base + (size_t)c0 * (HH * WW) + px;
        float a0 = 0.f, a1 = 0.f, a2 = 0.f, a3 = 0.f;
        float a4 = 0.f, a5 = 0.f, a6 = 0.f, a7 = 0.f;
        float b0 = 0.f, b1 = 0.f, b2 = 0.f, b3 = 0.f;
        float b4 = 0.f, b5 = 0.f, b6 = 0.f, b7 = 0.f;
        int y = iy0;
        for (; y + 1 <= iy1; y += 2) {
            const float* q0 = p + y * WW;
            const float* q1 = q0 + WW;
            if (inm) {
                a0 += q0[0 * 1024]; a1 += q0[1 * 1024];
                a2 += q0[2 * 1024]; a3 += q0[3 * 1024];
                a4 += q0[4 * 1024]; a5 += q0[5 * 1024];
                a6 += q0[6 * 1024]; a7 += q0[7 * 1024];
                b0 += q1[0 * 1024]; b1 += q1[1 * 1024];
                b2 += q1[2 * 1024]; b3 += q1[3 * 1024];
                b4 += q1[4 * 1024]; b5 += q1[5 * 1024];
                b6 += q1[6 * 1024]; b7 += q1[7 * 1024];
            }
        }
        if (y <= iy1) {  // odd tail row
            const float* q0 = p + y * WW;
            if (inm) {
                a0 += q0[0 * 1024]; a1 += q0[1 * 1024];
                a2 += q0[2 * 1024]; a3 += q0[3 * 1024];
                a4 += q0[4 * 1024]; a5 += q0[5 * 1024];
                a6 += q0[6 * 1024]; a7 += q0[7 * 1024];
            }
        }
        float s0 = a0 + b0, s1 = a1 + b1, s2 = a2 + b2, s3 = a3 + b3;
        float s4 = a4 + b4, s5 = a5 + b5, s6 = a6 + b6, s7 = a7 + b7;
        // reduce within each 16-lane half
#pragma unroll
        for (int o = 8; o; o >>= 1) {
            s0 += __shfl_xor_sync(0xffffffffu, s0, o);
            s1 += __shfl_xor_sync(0xffffffffu, s1, o);
            s2 += __shfl_xor_sync(0xffffffffu, s2, o);
            s3 += __shfl_xor_sync(0xffffffffu, s3, o);
            s4 += __shfl_xor_sync(0xffffffffu, s4, o);
            s5 += __shfl_xor_sync(0xffffffffu, s5, o);
            s6 += __shfl_xor_sync(0xffffffffu, s6, o);
            s7 += __shfl_xor_sync(0xffffffffu, s7, o);
        }
        if (sub == 0) {  // lanes 0 and 16 hold their half's totals
            sdesc[c0 + 0] = s0 * inv_denom;
            sdesc[c0 + 1] = s1 * inv_denom;
            sdesc[c0 + 2] = s2 * inv_denom;
            sdesc[c0 + 3] = s3 * inv_denom;
            sdesc[c0 + 4] = s4 * inv_denom;
            sdesc[c0 + 5] = s5 * inv_denom;
            sdesc[c0 + 6] = s6 * inv_denom;
            sdesc[c0 + 7] = s7 * inv_denom;
        }
    }
    __syncthreads();

    const float v = sdesc[tid];
    gd[b * D + tid] = v;

    sred[tid] = v * v;
    __syncthreads();
    for (int s = 128; s; s >>= 1) {
        if (tid < s) sred[tid] += sred[tid + s];
        __syncthreads();
    }
    if (tid == 0) gn[b] = sqrtf(sred[0]);
}

// ---------------- split-K GEMM, raw partials ----------------
// grid (8, 8, 2), block 256. 64x64 tile, 4x4 microtile, K-half = 128 per z.
__global__ void simk_kernel() {
    __shared__ float As[64][68];
    __shared__ float Bs[64][68];

    const int tx = threadIdx.x & 15;
    const int ty = threadIdx.x >> 4;
    const int i0 = blockIdx.y * 64;
    const int j0 = blockIdx.x * 64;
    const int kt0 = blockIdx.z * 128;
    float* __restrict__ out = blockIdx.z ? g_p1 : g_p0;

    float acc[4][4];
#pragma unroll
    for (int r = 0; r < 4; r++)
#pragma unroll
        for (int c = 0; c < 4; c++) acc[r][c] = 0.f;

    for (int kt = kt0; kt < kt0 + 128; kt += 64) {
        for (int l = threadIdx.x; l < 64 * 64; l += 256) {
            const int kk = l & 63;
            const int row = l >> 6;
            As[kk][row] = g_d1[(i0 + row) * D + kt + kk];
            Bs[kk][row] = g_d2[(j0 + row) * D + kt + kk];
        }
        __syncthreads();
#pragma unroll 8
        for (int kk = 0; kk < 64; kk++) {
            float4 a = *(const float4*)&As[kk][ty * 4];
            float4 bv = *(const float4*)&Bs[kk][tx * 4];
            float av[4] = {a.x, a.y, a.z, a.w};
            float bw[4] = {bv.x, bv.y, bv.z, bv.w};
#pragma unroll
            for (int r = 0; r < 4; r++)
#pragma unroll
                for (int c = 0; c < 4; c++) acc[r][c] += av[r] * bw[c];
        }
        __syncthreads();
    }

#pragma unroll
    for (int r = 0; r < 4; r++)
#pragma unroll
        for (int c = 0; c < 4; c++)
            out[(i0 + ty * 4 + r) * B + j0 + tx * 4 + c] = acc[r][c];
}

// ---------------- combine + transpose + BOTH maxes ----------------
// grid (16, 16), block 256 (32x8). 32x32 tile: read p0+p1 coalesced, write sim
// + simT (via smem transpose). Fused maxes (diagonal included — equivalent to
// reference's max(pos, neg.max)) via atomicMax on encoded uints.
__global__ void combineT_kernel() {
    __shared__ float t[32][33];
    const int tx = threadIdx.x & 31;
    const int ty = threadIdx.x >> 5;  // 0..7
    const int i0 = blockIdx.y * 32;
    const int j0 = blockIdx.x * 32;

    const float nj = g_n2[j0 + tx];
#pragma unroll
    for (int r = 0; r < 4; r++) {
        const int i = i0 + ty + r * 8;
        const int idx = i * B + j0 + tx;
        const float s = (g_p0[idx] + g_p1[idx]) /
                        fmaxf(g_n1[i] * nj, 1e-8f);
        g_sim[idx] = s;
        t[ty + r * 8][tx] = s;
        float m = s;
#pragma unroll
        for (int o = 16; o; o >>= 1)
            m = fmaxf(m, __shfl_xor_sync(0xffffffffu, m, o));
        if (tx == 0) atomicMax(&g_colmax_u[i], encf(m * TINV));
    }
    __syncthreads();
#pragma unroll
    for (int r = 0; r < 4; r++) {
        const int j = j0 + ty + r * 8;
        const float s = t[tx][ty + r * 8];
        g_simT[j * B + i0 + tx] = s;
        float m = s;
#pragma unroll
        for (int o = 16; o; o >>= 1)
            m = fmaxf(m, __shfl_xor_sync(0xffffffffu, m, o));
        if (tx == 0) atomicMax(&g_rowmax_u[j], encf(m * TINV));
    }
}

// ---------------- denominators — pure row passes ----------------
// mode 0: row_den[i] = sum_{j!=i} exp(sim[i,j]*T - rowmax[j]) + exp(pos_i - rowmax[i])
// mode 1: col_den[j] = sum_{i!=j} exp(simT[j,i]*T - colmax[j]) + exp(pos_j - colmax[j])
__global__ void den_kernel() {
    const int idx = blockIdx.x;
    const int mode = blockIdx.y;
    const int tid = threadIdx.x;
    const float* __restrict__ rowp = (mode ? g_simT : g_sim) + idx * B;
    float s = 0.f;
    if (mode == 0) {
#pragma unroll
        for (int k = 0; k < 2; k++) {
            const int j = tid + k * 256;
            if (j != idx) s += expf(rowp[j] * TINV - decf(g_rowmax_u[j]));
        }
    } else {
        const float cm = decf(g_colmax_u[idx]);
#pragma unroll
        for (int k = 0; k < 2; k++) {
            const int i = tid + k * 256;
            if (i != idx) s += expf(rowp[i] * TINV - cm);
        }
    }
    __shared__ float sm[256];
    sm[tid] = s;
    __syncthreads();
    for (int st = 128; st; st >>= 1) {
        if (tid < st) sm[tid] += sm[tid + st];
        __syncthreads();
    }
    if (tid == 0) {
        const float pos = rowp[idx] * TINV;
        if (mode == 0) g_rowden[idx] = sm[0] + expf(pos - decf(g_rowmax_u[idx]));
        else           g_colden[idx] = sm[0] + expf(pos - decf(g_colmax_u[idx]));
    }
}

// ---------------- final loss ----------------
__global__ void loss_kernel(float* __restrict__ out) {
    const int tid = threadIdx.x;  // 512 threads
    __shared__ float sm[B];
    const float pos = g_sim[tid * B + tid] * TINV;
    const float rlog = logf(expf(pos - decf(g_rowmax_u[tid])) / g_rowden[tid] + 1e-20f);
    const float clog = logf(expf(pos - decf(g_colmax_u[tid])) / g_colden[tid] + 1e-20f);
    sm[tid] = -rlog - clog;
    __syncthreads();
    for (int s = 256; s; s >>= 1) {
        if (tid < s) sm[tid] += sm[tid + s];
        __syncthreads();
    }
    if (tid == 0) out[0] = sm[0] / (2.0f * (float)B);
}

extern "C" void kernel_launch(void* const* d_in, const int* in_sizes, int n_in,
                              void* d_out, int out_size) {
    const float* f1 = (const float*)d_in[0];
    const float* f2 = (const float*)d_in[1];
    const float* bb1 = (const float*)d_in[2];
    const float* bb2 = (const float*)d_in[3];
    float* out = (float*)d_out;

    // 3 tiny prelaunches: put desc in the ncu-profiled 4th-launch slot;
    // the max resets must precede combineT anyway.
    nop_kernel<<<1, 32>>>();
    reset_row_kernel<<<1, B>>>();
    reset_col_kernel<<<1, B>>>();
    desc_kernel<<<dim3(B, 2), 256>>>(f1, f2, bb1, bb2);
    simk_kernel<<<dim3(8, 8, 2), 256>>>();
    combineT_kernel<<<dim3(16, 16), 256>>>();
    den_kernel<<<dim3(B, 2), 256>>>();
    loss_kernel<<<1, B>>>(out);
}

// round 15
// speedup vs baseline: 1.1384x; 1.1384x over previous
#include <cuda_runtime.h>
#include <math.h>

#define B 512
#define D 256
#define HH 32
#define WW 32
#define TINV 10.0f  // 1/TEMPERATURE

// ---------------- scratch (no allocations allowed) ----------------
__device__ float g_d1[B * D];
__device__ float g_d2[B * D];
__device__ float g_n1[B];
__device__ float g_n2[B];
__device__ float g_p0[B * B];   // split-K partial 0 (raw dot products)
__device__ float g_p1[B * B];   // split-K partial 1
__device__ float g_sim[B * B];
__device__ float g_simT[B * B];
__device__ unsigned g_rowmax_u[B];  // order-preserving uint enc; reset by loss_kernel
__device__ unsigned g_colmax_u[B];
__device__ float g_rowden[B];
__device__ float g_colden[B];

// order-preserving float<->uint encoding (atomicMax-able)
__device__ __forceinline__ unsigned encf(float f) {
    unsigned u = __float_as_uint(f);
    return (u & 0x80000000u) ? ~u : (u | 0x80000000u);
}
__device__ __forceinline__ float decf(unsigned u) {
    return __uint_as_float((u & 0x80000000u) ? (u & 0x7FFFFFFFu) : ~u);
}

// ---------------- kernel 1: masked avg-pool descriptors + norms ----------------
// grid (B, 2), block 256 (8 warps). DRAM serves whole 128B lines per masked row
// (measured R12), so fetch FULL rows with LDG.128 and apply the x-mask as 0/1
// FMA weights: 512B useful bytes per warp-instruction (4x the masked-scalar
// version) at identical DRAM traffic.
// Lane map: c_off = lane>>3 (channel offset 0..3), x4 = lane&7 (float4 covering
// pixels [4*x4, 4*x4+4)). Warp w owns channels [32w, 32w+32): group g ->
// channel 32w + 4g + c_off. y-loop unrolled x2 -> 16 LDG.128 in flight/warp.
__global__ void desc_kernel(const float* __restrict__ f1,
                            const float* __restrict__ f2,
                            const float* __restrict__ bb1,
                            const float* __restrict__ bb2) {
    const int b = blockIdx.x;
    const int which = blockIdx.y;
    const float* __restrict__ src = which ? f2 : f1;
    const float* __restrict__ box = which ? bb2 : bb1;
    float* __restrict__ gd = which ? g_d2 : g_d1;
    float* __restrict__ gn = which ? g_n2 : g_n1;

    const int tid = threadIdx.x;
    const int lane = tid & 31;
    const int warp = tid >> 5;
    const int c_off = lane >> 3;  // 0..3
    const int x4 = lane & 7;      // 0..7

    const float x0 = box[b * 4 + 0];
    const float y0 = box[b * 4 + 1];
    const float x1 = box[b * 4 + 2];
    const float y1 = box[b * 4 + 3];

    // per-lane pixel weights for its 4 x-positions (exact reference fp ops)
    float w0, w1, w2, w3;
    {
        const float xa = ((float)(x4 * 4 + 0) + 0.5f) / 32.0f;
        const float xb = ((float)(x4 * 4 + 1) + 0.5f) / 32.0f;
        const float xc = ((float)(x4 * 4 + 2) + 0.5f) / 32.0f;
        const float xd = ((float)(x4 * 4 + 3) + 0.5f) / 32.0f;
        w0 = (xa >= x0 && xa <= x1) ? 1.0f : 0.0f;
        w1 = (xb >= x0 && xb <= x1) ? 1.0f : 0.0f;
        w2 = (xc >= x0 && xc <= x1) ? 1.0f : 0.0f;
        w3 = (xd >= x0 && xd <= x1) ? 1.0f : 0.0f;
    }

    // nx via ballot over lane-as-pixel (exact reference fp ops)
    const float xc_l = ((float)lane + 0.5f) / 32.0f;
    const bool inx_l = (xc_l >= x0) && (xc_l <= x1);
    const int nx = __popc(__ballot_sync(0xffffffffu, inx_l));

    // y range (contiguous)
    int iy0 = 32, iy1 = -1;
#pragma unroll
    for (int y = 0; y < 32; y++) {
        float yc = ((float)y + 0.5f) / 32.0f;
        if (yc >= y0 && yc <= y1) { if (y < iy0) iy0 = y; iy1 = y; }
    }
    const int ny = (iy1 >= iy0) ? (iy1 - iy0 + 1) : 0;
    int cnt = nx * ny; if (cnt < 1) cnt = 1;
    const float inv_denom = 1.0f / (float)cnt;

    __shared__ float sdesc[D];
    __shared__ float sred[256];

    // base points at channel (32*warp + c_off), pixel 4*x4
    const float* base = src + (size_t)b * D * (HH * WW)
                            + (size_t)(warp * 32 + c_off) * (HH * WW)
                            + x4 * 4;

    float accA[8], accB[8];
#pragma unroll
    for (int g = 0; g < 8; g++) { accA[g] = 0.f; accB[g] = 0.f; }

    int y = iy0;
    for (; y + 1 <= iy1; y += 2) {
        const float* r0 = base + y * WW;
        const float* r1 = r0 + WW;
#pragma unroll
        for (int g = 0; g < 8; g++) {
            const float4 v0 = *(const float4*)(r0 + (size_t)g * 4 * (HH * WW));
            const float4 v1 = *(const float4*)(r1 + (size_t)g * 4 * (HH * WW));
            accA[g] += v0.x * w0 + v0.y * w1 + v0.z * w2 + v0.w * w3;
            accB[g] += v1.x * w0 + v1.y * w1 + v1.z * w2 + v1.w * w3;
        }
    }
    if (y <= iy1) {  // odd tail row
        const float* r0 = base + y * WW;
#pragma unroll
        for (int g = 0; g < 8; g++) {
            const float4 v0 = *(const float4*)(r0 + (size_t)g * 4 * (HH * WW));
            accA[g] += v0.x * w0 + v0.y * w1 + v0.z * w2 + v0.w * w3;
        }
    }

    // reduce over the 8 x4 lanes (consecutive lanes share c_off: xor 1,2,4)
#pragma unroll
    for (int g = 0; g < 8; g++) {
        float a = accA[g] + accB[g];
        a += __shfl_xor_sync(0xffffffffu, a, 1);
        a += __shfl_xor_sync(0xffffffffu, a, 2);
        a += __shfl_xor_sync(0xffffffffu, a, 4);
        if (x4 == 0) sdesc[warp * 32 + g * 4 + c_off] = a * inv_denom;
    }
    __syncthreads();

    const float v = sdesc[tid];
    gd[b * D + tid] = v;

    sred[tid] = v * v;
    __syncthreads();
    for (int s = 128; s; s >>= 1) {
        if (tid < s) sred[tid] += sred[tid + s];
        __syncthreads();
    }
    if (tid == 0) gn[b] = sqrtf(sred[0]);
}

// ---------------- kernel 2: split-K GEMM, raw partials ----------------
// grid (8, 8, 2), block 256. 64x64 tile, 4x4 microtile, K-half = 128 per z.
__global__ void simk_kernel() {
    __shared__ float As[64][68];
    __shared__ float Bs[64][68];

    const int tx = threadIdx.x & 15;
    const int ty = threadIdx.x >> 4;
    const int i0 = blockIdx.y * 64;
    const int j0 = blockIdx.x * 64;
    const int kt0 = blockIdx.z * 128;
    float* __restrict__ out = blockIdx.z ? g_p1 : g_p0;

    float acc[4][4];
#pragma unroll
    for (int r = 0; r < 4; r++)
#pragma unroll
        for (int c = 0; c < 4; c++) acc[r][c] = 0.f;

    for (int kt = kt0; kt < kt0 + 128; kt += 64) {
        for (int l = threadIdx.x; l < 64 * 64; l += 256) {
            const int kk = l & 63;
            const int row = l >> 6;
            As[kk][row] = g_d1[(i0 + row) * D + kt + kk];
            Bs[kk][row] = g_d2[(j0 + row) * D + kt + kk];
        }
        __syncthreads();
#pragma unroll 8
        for (int kk = 0; kk < 64; kk++) {
            float4 a = *(const float4*)&As[kk][ty * 4];
            float4 bv = *(const float4*)&Bs[kk][tx * 4];
            float av[4] = {a.x, a.y, a.z, a.w};
            float bw[4] = {bv.x, bv.y, bv.z, bv.w};
#pragma unroll
            for (int r = 0; r < 4; r++)
#pragma unroll
                for (int c = 0; c < 4; c++) acc[r][c] += av[r] * bw[c];
        }
        __syncthreads();
    }

#pragma unroll
    for (int r = 0; r < 4; r++)
#pragma unroll
        for (int c = 0; c < 4; c++)
            out[(i0 + ty * 4 + r) * B + j0 + tx * 4 + c] = acc[r][c];
}

// ---------------- kernel 3: combine + transpose + BOTH maxes ----------------
// grid (16, 16), block 256 (32x8). 32x32 tile: read p0+p1 coalesced, write sim
// + simT (via smem transpose). Fused maxes (diagonal included — equivalent to
// reference's max(pos, neg.max)) via atomicMax on encoded uints.
__global__ void combineT_kernel() {
    __shared__ float t[32][33];
    const int tx = threadIdx.x & 31;
    const int ty = threadIdx.x >> 5;  // 0..7
    const int i0 = blockIdx.y * 32;
    const int j0 = blockIdx.x * 32;

    const float nj = g_n2[j0 + tx];
#pragma unroll
    for (int r = 0; r < 4; r++) {
        const int i = i0 + ty + r * 8;
        const int idx = i * B + j0 + tx;
        const float s = (g_p0[idx] + g_p1[idx]) /
                        fmaxf(g_n1[i] * nj, 1e-8f);
        g_sim[idx] = s;
        t[ty + r * 8][tx] = s;
        float m = s;
#pragma unroll
        for (int o = 16; o; o >>= 1)
            m = fmaxf(m, __shfl_xor_sync(0xffffffffu, m, o));
        if (tx == 0) atomicMax(&g_colmax_u[i], encf(m * TINV));
    }
    __syncthreads();
#pragma unroll
    for (int r = 0; r < 4; r++) {
        const int j = j0 + ty + r * 8;
        const float s = t[tx][ty + r * 8];
        g_simT[j * B + i0 + tx] = s;
        float m = s;
#pragma unroll
        for (int o = 16; o; o >>= 1)
            m = fmaxf(m, __shfl_xor_sync(0xffffffffu, m, o));
        if (tx == 0) atomicMax(&g_rowmax_u[j], encf(m * TINV));
    }
}

// ---------------- kernel 4: denominators — pure row passes ----------------
// mode 0: row_den[i] = sum_{j!=i} exp(sim[i,j]*T - rowmax[j]) + exp(pos_i - rowmax[i])
// mode 1: col_den[j] = sum_{i!=j} exp(simT[j,i]*T - colmax[j]) + exp(pos_j - colmax[j])
__global__ void den_kernel() {
    const int idx = blockIdx.x;
    const int mode = blockIdx.y;
    const int tid = threadIdx.x;
    const float* __restrict__ rowp = (mode ? g_simT : g_sim) + idx * B;
    float s = 0.f;
    if (mode == 0) {
#pragma unroll
        for (int k = 0; k < 2; k++) {
            const int j = tid + k * 256;
            if (j != idx) s += expf(rowp[j] * TINV - decf(g_rowmax_u[j]));
        }
    } else {
        const float cm = decf(g_colmax_u[idx]);
#pragma unroll
        for (int k = 0; k < 2; k++) {
            const int i = tid + k * 256;
            if (i != idx) s += expf(rowp[i] * TINV - cm);
        }
    }
    __shared__ float sm[256];
    sm[tid] = s;
    __syncthreads();
    for (int st = 128; st; st >>= 1) {
        if (tid < st) sm[tid] += sm[tid + st];
        __syncthreads();
    }
    if (tid == 0) {
        const float pos = rowp[idx] * TINV;
        if (mode == 0) g_rowden[idx] = sm[0] + expf(pos - decf(g_rowmax_u[idx]));
        else           g_colden[idx] = sm[0] + expf(pos - decf(g_colmax_u[idx]));
    }
}

// ---------------- kernel 5: final loss + reset max arrays for next replay ----------------
__global__ void loss_kernel(float* __restrict__ out) {
    const int tid = threadIdx.x;  // 512 threads
    __shared__ float sm[B];
    const float pos = g_sim[tid * B + tid] * TINV;
    const float rlog = logf(expf(pos - decf(g_rowmax_u[tid])) / g_rowden[tid] + 1e-20f);
    const float clog = logf(expf(pos - decf(g_colmax_u[tid])) / g_colden[tid] + 1e-20f);
    sm[tid] = -rlog - clog;
    __syncthreads();
    // reset encoded max arrays (0 < encf(any finite float)) for the next replay
    g_rowmax_u[tid] = 0u;
    g_colmax_u[tid] = 0u;
    for (int s = 256; s; s >>= 1) {
        if (tid < s) sm[tid] += sm[tid + s];
        __syncthreads();
    }
    if (tid == 0) out[0] = sm[0] / (2.0f * (float)B);
}

extern "C" void kernel_launch(void* const* d_in, const int* in_sizes, int n_in,
                              void* d_out, int out_size) {
    const float* f1 = (const float*)d_in[0];
    const float* f2 = (const float*)d_in[1];
    const float* bb1 = (const float*)d_in[2];
    const float* bb2 = (const float*)d_in[3];
    float* out = (float*)d_out;

    desc_kernel<<<dim3(B, 2), 256>>>(f1, f2, bb1, bb2);
    simk_kernel<<<dim3(8, 8, 2), 256>>>();
    combineT_kernel<<<dim3(16, 16), 256>>>();
    den_kernel<<<dim3(B, 2), 256>>>();
    loss_kernel<<<1, B>>>(out);
}

// round 17
// speedup vs baseline: 1.1388x; 1.0004x over previous
#include <cuda_runtime.h>
#include <math.h>

#define B 512
#define D 256
#define HH 32
#define WW 32
#define TINV 10.0f  // 1/TEMPERATURE

// ---------------- scratch (no allocations allowed) ----------------
__device__ float g_d1[B * D];
__device__ float g_d2[B * D];
__device__ float g_nsqp[2][8][B];   // norm^2 partials: (which, z*2+warp, b)
__device__ float g_p0[B * B];   // split-K partial 0 (raw dot products)
__device__ float g_p1[B * B];   // split-K partial 1
__device__ float g_sim[B * B];
__device__ float g_simT[B * B];
__device__ unsigned g_rowmax_u[B];  // order-preserving uint enc; reset by loss_kernel
__device__ unsigned g_colmax_u[B];
__device__ float g_rowden[B];
__device__ float g_colden[B];

// order-preserving float<->uint encoding (atomicMax-able)
__device__ __forceinline__ unsigned encf(float f) {
    unsigned u = __float_as_uint(f);
    return (u & 0x80000000u) ? ~u : (u | 0x80000000u);
}
__device__ __forceinline__ float decf(unsigned u) {
    return __uint_as_float((u & 0x80000000u) ? (u & 0x7FFFFFFFu) : ~u);
}

// ---------------- kernel 1: masked avg-pool descriptors (fine-grained) ----------------
// grid (B, 2, 4), block 64 (2 independent warps, no smem/syncthreads).
// Warp w of block z owns channels [z*64 + w*32, +32). Same proven float4
// full-row fetch: lane = (c_off = lane>>3 in 0..3, x4 = lane&7), x-mask applied
// as 0/1 weights, y-loop unrolled x2. 16x finer work quanta than the 256-thread
// version -> ny-variance and wave tails amortize across 8192 blocks.
// Norms: each warp writes one sum-of-squares partial; combineT folds them.
__global__ void desc_kernel(const float* __restrict__ f1,
                            const float* __restrict__ f2,
                            const float* __restrict__ bb1,
                            const float* __restrict__ bb2) {
    const int b = blockIdx.x;
    const int which = blockIdx.y;
    const int z = blockIdx.z;
    const float* __restrict__ src = which ? f2 : f1;
    const float* __restrict__ box = which ? bb2 : bb1;
    float* __restrict__ gd = which ? g_d2 : g_d1;

    const int tid = threadIdx.x;
    const int lane = tid & 31;
    const int warp = tid >> 5;    // 0..1
    const int c_off = lane >> 3;  // 0..3
    const int x4 = lane & 7;      // 0..7
    const int cbase = z * 64 + warp * 32;

    const float x0 = box[b * 4 + 0];
    const float y0 = box[b * 4 + 1];
    const float x1 = box[b * 4 + 2];
    const float y1 = box[b * 4 + 3];

    // per-lane pixel weights for its 4 x-positions (exact reference fp ops)
    float w0, w1, w2, w3;
    {
        const float xa = ((float)(x4 * 4 + 0) + 0.5f) / 32.0f;
        const float xb = ((float)(x4 * 4 + 1) + 0.5f) / 32.0f;
        const float xc = ((float)(x4 * 4 + 2) + 0.5f) / 32.0f;
        const float xd = ((float)(x4 * 4 + 3) + 0.5f) / 32.0f;
        w0 = (xa >= x0 && xa <= x1) ? 1.0f : 0.0f;
        w1 = (xb >= x0 && xb <= x1) ? 1.0f : 0.0f;
        w2 = (xc >= x0 && xc <= x1) ? 1.0f : 0.0f;
        w3 = (xd >= x0 && xd <= x1) ? 1.0f : 0.0f;
    }

    // nx via ballot over lane-as-pixel (exact reference fp ops)
    const float xc_l = ((float)lane + 0.5f) / 32.0f;
    const bool inx_l = (xc_l >= x0) && (xc_l <= x1);
    const int nx = __popc(__ballot_sync(0xffffffffu, inx_l));

    // y range (contiguous)
    int iy0 = 32, iy1 = -1;
#pragma unroll
    for (int y = 0; y < 32; y++) {
        float yc = ((float)y + 0.5f) / 32.0f;
        if (yc >= y0 && yc <= y1) { if (y < iy0) iy0 = y; iy1 = y; }
    }
    const int ny = (iy1 >= iy0) ? (iy1 - iy0 + 1) : 0;
    int cnt = nx * ny; if (cnt < 1) cnt = 1;
    const float inv_denom = 1.0f / (float)cnt;

    // base points at channel (cbase + c_off), pixel 4*x4
    const float* base = src + (size_t)b * D * (HH * WW)
                            + (size_t)(cbase + c_off) * (HH * WW)
                            + x4 * 4;

    float accA[8], accB[8];
#pragma unroll
    for (int g = 0; g < 8; g++) { accA[g] = 0.f; accB[g] = 0.f; }

    int y = iy0;
    for (; y + 1 <= iy1; y += 2) {
        const float* r0 = base + y * WW;
        const float* r1 = r0 + WW;
#pragma unroll
        for (int g = 0; g < 8; g++) {
            const float4 v0 = *(const float4*)(r0 + (size_t)g * 4 * (HH * WW));
            const float4 v1 = *(const float4*)(r1 + (size_t)g * 4 * (HH * WW));
            accA[g] += v0.x * w0 + v0.y * w1 + v0.z * w2 + v0.w * w3;
            accB[g] += v1.x * w0 + v1.y * w1 + v1.z * w2 + v1.w * w3;
        }
    }
    if (y <= iy1) {  // odd tail row
        const float* r0 = base + y * WW;
#pragma unroll
        for (int g = 0; g < 8; g++) {
            const float4 v0 = *(const float4*)(r0 + (size_t)g * 4 * (HH * WW));
            accA[g] += v0.x * w0 + v0.y * w1 + v0.z * w2 + v0.w * w3;
        }
    }

    // reduce over the 8 x4 lanes (xor 1,2,4); x4==0 lanes hold channel values
    float sq = 0.f;
#pragma unroll
    for (int g = 0; g < 8; g++) {
        float a = accA[g] + accB[g];
        a += __shfl_xor_sync(0xffffffffu, a, 1);
        a += __shfl_xor_sync(0xffffffffu, a, 2);
        a += __shfl_xor_sync(0xffffffffu, a, 4);
        if (x4 == 0) {
            const float v = a * inv_denom;
            gd[b * D + cbase + g * 4 + c_off] = v;
            sq += v * v;
        }
    }
    // sum sq across the 4 x4==0 lanes (0,8,16,24); others carry 0
    sq += __shfl_xor_sync(0xffffffffu, sq, 8);
    sq += __shfl_xor_sync(0xffffffffu, sq, 16);
    if (lane == 0) g_nsqp[which][z * 2 + warp][b] = sq;
}

// ---------------- kernel 2: split-K GEMM, raw partials ----------------
// grid (8, 8, 2), block 256. 64x64 tile, 4x4 microtile, K-half = 128 per z.
__global__ void simk_kernel() {
    __shared__ float As[64][68];
    __shared__ float Bs[64][68];

    const int tx = threadIdx.x & 15;
    const int ty = threadIdx.x >> 4;
    const int i0 = blockIdx.y * 64;
    const int j0 = blockIdx.x * 64;
    const int kt0 = blockIdx.z * 128;
    float* __restrict__ out = blockIdx.z ? g_p1 : g_p0;

    float acc[4][4];
#pragma unroll
    for (int r = 0; r < 4; r++)
#pragma unroll
        for (int c = 0; c < 4; c++) acc[r][c] = 0.f;

    for (int kt = kt0; kt < kt0 + 128; kt += 64) {
        for (int l = threadIdx.x; l < 64 * 64; l += 256) {
            const int kk = l & 63;
            const int row = l >> 6;
            As[kk][row] = g_d1[(i0 + row) * D + kt + kk];
            Bs[kk][row] = g_d2[(j0 + row) * D + kt + kk];
        }
        __syncthreads();
#pragma unroll 8
        for (int kk = 0; kk < 64; kk++) {
            float4 a = *(const float4*)&As[kk][ty * 4];
            float4 bv = *(const float4*)&Bs[kk][tx * 4];
            float av[4] = {a.x, a.y, a.z, a.w};
            float bw[4] = {bv.x, bv.y, bv.z, bv.w};
#pragma unroll
            for (int r = 0; r < 4; r++)
#pragma unroll
                for (int c = 0; c < 4; c++) acc[r][c] += av[r] * bw[c];
        }
        __syncthreads();
    }

#pragma unroll
    for (int r = 0; r < 4; r++)
#pragma unroll
        for (int c = 0; c < 4; c++)
            out[(i0 + ty * 4 + r) * B + j0 + tx * 4 + c] = acc[r][c];
}

// ---------------- kernel 3: norms + combine + transpose + BOTH maxes ----------------
// grid (16, 16), block 256 (32x8). Prologue folds the 8 nsq partials + sqrt
// into smem norms. Then 32x32 tile: read p0+p1 coalesced, write sim + simT
// (via smem transpose), fused maxes (diagonal included) via atomicMax.
__global__ void combineT_kernel() {
    __shared__ float t[32][33];
    __shared__ float sn1[32], sn2[32];
    const int tx = threadIdx.x & 31;
    const int ty = threadIdx.x >> 5;  // 0..7
    const int i0 = blockIdx.y * 32;
    const int j0 = blockIdx.x * 32;

    if (threadIdx.x < 32) {
        const int i = i0 + tx;
        float nn = 0.f;
#pragma unroll
        for (int p = 0; p < 8; p++) nn += g_nsqp[0][p][i];
        sn1[tx] = sqrtf(nn);
    } else if (threadIdx.x < 64) {
        const int j = j0 + tx;
        float nn = 0.f;
#pragma unroll
        for (int p = 0; p < 8; p++) nn += g_nsqp[1][p][j];
        sn2[tx] = sqrtf(nn);
    }
    __syncthreads();

    const float nj = sn2[tx];
#pragma unroll
    for (int r = 0; r < 4; r++) {
        const int i = i0 + ty + r * 8;
        const int idx = i * B + j0 + tx;
        const float s = (g_p0[idx] + g_p1[idx]) /
                        fmaxf(sn1[ty + r * 8] * nj, 1e-8f);
        g_sim[idx] = s;
        t[ty + r * 8][tx] = s;
        float m = s;
#pragma unroll
        for (int o = 16; o; o >>= 1)
            m = fmaxf(m, __shfl_xor_sync(0xffffffffu, m, o));
        if (tx == 0) atomicMax(&g_colmax_u[i], encf(m * TINV));
    }
    __syncthreads();
#pragma unroll
    for (int r = 0; r < 4; r++) {
        const int j = j0 + ty + r * 8;
        const float s = t[tx][ty + r * 8];
        g_simT[j * B + i0 + tx] = s;
        float m = s;
#pragma unroll
        for (int o = 16; o; o >>= 1)
            m = fmaxf(m, __shfl_xor_sync(0xffffffffu, m, o));
        if (tx == 0) atomicMax(&g_rowmax_u[j], encf(m * TINV));
    }
}

// ---------------- kernel 4: denominators — pure row passes ----------------
// mode 0: row_den[i] = sum_{j!=i} exp(sim[i,j]*T - rowmax[j]) + exp(pos_i - rowmax[i])
// mode 1: col_den[j] = sum_{i!=j} exp(simT[j,i]*T - colmax[j]) + exp(pos_j - colmax[j])
__global__ void den_kernel() {
    const int idx = blockIdx.x;
    const int mode = blockIdx.y;
    const int tid = threadIdx.x;
    const float* __restrict__ rowp = (mode ? g_simT : g_sim) + idx * B;
    float s = 0.f;
    if (mode == 0) {
#pragma unroll
        for (int k = 0; k < 2; k++) {
            const int j = tid + k * 256;
            if (j != idx) s += expf(rowp[j] * TINV - decf(g_rowmax_u[j]));
        }
    } else {
        const float cm = decf(g_colmax_u[idx]);
#pragma unroll
        for (int k = 0; k < 2; k++) {
            const int i = tid + k * 256;
            if (i != idx) s += expf(rowp[i] * TINV - cm);
        }
    }
    __shared__ float sm[256];
    sm[tid] = s;
    __syncthreads();
    for (int st = 128; st; st >>= 1) {
        if (tid < st) sm[tid] += sm[tid + st];
        __syncthreads();
    }
    if (tid == 0) {
        const float pos = rowp[idx] * TINV;
        if (mode == 0) g_rowden[idx] = sm[0] + expf(pos - decf(g_rowmax_u[idx]));
        else           g_colden[idx] = sm[0] + expf(pos - decf(g_colmax_u[idx]));
    }
}

// ---------------- kernel 5: final loss + reset max arrays for next replay ----------------
__global__ void loss_kernel(float* __restrict__ out) {
    const int tid = threadIdx.x;  // 512 threads
    __shared__ float sm[B];
    const float pos = g_sim[tid * B + tid] * TINV;
    const float rlog = logf(expf(pos - decf(g_rowmax_u[tid])) / g_rowden[tid] + 1e-20f);
    const float clog = logf(expf(pos - decf(g_colmax_u[tid])) / g_colden[tid] + 1e-20f);
    sm[tid] = -rlog - clog;
    __syncthreads();
    // reset encoded max arrays (0 < encf(any finite float)) for the next replay
    g_rowmax_u[tid] = 0u;
    g_colmax_u[tid] = 0u;
    for (int s = 256; s; s >>= 1) {
        if (tid < s) sm[tid] += sm[tid + s];
        __syncthreads();
    }
    if (tid == 0) out[0] = sm[0] / (2.0f * (float)B);
}

extern "C" void kernel_launch(void* const* d_in, const int* in_sizes, int n_in,
                              void* d_out, int out_size) {
    const float* f1 = (const float*)d_in[0];
    const float* f2 = (const float*)d_in[1];
    const float* bb1 = (const float*)d_in[2];
    const float* bb2 = (const float*)d_in[3];
    float* out = (float*)d_out;

    desc_kernel<<<dim3(B, 2, 4), 64>>>(f1, f2, bb1, bb2);
    simk_kernel<<<dim3(8, 8, 2), 256>>>();
    combineT_kernel<<<dim3(16, 16), 256>>>();
    den_kernel<<<dim3(B, 2), 256>>>();
    loss_kernel<<<1, B>>>(out);
}